// round 15
// baseline (speedup 1.0000x reference)
#include <cuda_runtime.h>
#include <cuda_bf16.h>
#include <math.h>

// Fixed shapes
#define BB 2
#define PP 600
#define FF 1024
#define HH 80
#define WW 80
#define TH 256
#define TW 256
#define SIGMA 7e-5f
#define DEG_EPS 1e-8f
#define SKIP_S 0.09f   // distance beyond which expf(-d2/SIGMA) == 0.0f exactly
#define NEG_INV_SIGMA (-1.0f / SIGMA)

// Output layout: imrender (B,H,W,3) | improb (B,H,W,1) | normal1 (B,F,3) | mask (B,H,W,1)
#define OFF_IMPROB (BB*HH*WW*3)
#define OFF_NORMAL (OFF_IMPROB + BB*HH*WW)
#define OFF_MASK   (OFF_NORMAL + BB*FF*3)

// Per-batch compacted front-face rows, 32 floats = 8 float4:
// bb [ 0.. 3] bbox minx,miny,maxx,maxy (expanded by SKIP_S margin)
// q0 [ 4.. 7] e0x,e0y,e0d,e1x
// q1 [ 8..11] e1y,e1d,e2x,e2y
// q2 [12..15] e2d,inv,x2,y2
// q3 [16..19] A0,B0,A1,B1     (A0=y1-y2,B0=x2-x1,A1=y2-y0,B1=x0-x2)
// q4 [20..23] z0,z1,z2,invL2_01   (edge v0->v1)
// q5 [24..27] x0,y0,x1,y1
// q6 [28..31] invL2_12, invL2_20, pad, pad
__device__ __align__(16) float g_face[BB][FF][32];
__device__ __align__(16) float g_uv[BB][FF][8];
__device__ int g_cnt[BB];

__device__ __forceinline__ void edge_eq(float ax, float ay, float bx, float by,
                                        float cx, float cy, float* o)
{
    const float ex = bx - ax, ey = by - ay;
    const float L2 = ex * ex + ey * ey;
    if (L2 < 1e-30f) { o[0] = 0.0f; o[1] = 0.0f; o[2] = -1.0f; return; }
    const float rL = rsqrtf(L2);
    float nx = ey * rL, ny = -ex * rL;
    float d = -(nx * ax + ny * ay);
    if (nx * cx + ny * cy + d > 0.0f) { nx = -nx; ny = -ny; d = -d; }
    o[0] = nx; o[1] = ny; o[2] = d;
}

// ---------------------------------------------------------------------------
// Setup: projection, normal1 output (XLA-FMA-contracted cross — load-bearing),
// stable front-face compaction, edge-eq + bbox + invL2 precompute.
// grid=(B), block=F
// ---------------------------------------------------------------------------
__global__ void setup_kernel(const float* __restrict__ points,
                             const int*   __restrict__ faces,
                             const float* __restrict__ camrot,
                             const float* __restrict__ campos,
                             const float* __restrict__ camproj,
                             const float* __restrict__ uv,
                             float* __restrict__ out)
{
    const int b = blockIdx.x;
    const int i = threadIdx.x;

    float r[9];
#pragma unroll
    for (int k = 0; k < 9; k++) r[k] = camrot[b * 9 + k];
    const float posx = campos[b * 3 + 0];
    const float posy = campos[b * 3 + 1];
    const float posz = campos[b * 3 + 2];
    const float pr0 = camproj[0], pr1 = camproj[1], pr2 = camproj[2];

    const int i0 = faces[i * 3 + 0];
    const int i1 = faces[i * 3 + 1];
    const int i2 = faces[i * 3 + 2];
    const int idxs[3] = { i0, i1, i2 };

    float vx[3], vy[3], vz[3], sx[3], sy[3];
#pragma unroll
    for (int k = 0; k < 3; k++) {
        const float* p = points + (b * PP + idxs[k]) * 3;
        const float qx = __fsub_rn(p[0], posx);
        const float qy = __fsub_rn(p[1], posy);
        const float qz = __fsub_rn(p[2], posz);
        // camrot is identity in this dataset -> exact regardless of fma
        const float pcx = r[0] * qx + r[1] * qy + r[2] * qz;
        const float pcy = r[3] * qx + r[4] * qy + r[5] * qz;
        const float pcz = r[6] * qx + r[7] * qy + r[8] * qz;
        vx[k] = pcx; vy[k] = pcy; vz[k] = pcz;
        const float zz = __fmul_rn(pcz, pr2);
        sx[k] = __fdiv_rn(__fmul_rn(pcx, pr0), zz);
        sy[k] = __fdiv_rn(__fmul_rn(pcy, pr1), zz);
    }

    // cross(v1-v0, v2-v0) with LLVM-canonical FMA contraction:
    // fsub(fmul x y, fmul c d) -> fma(x, y, -round(c*d)). Load-bearing for
    // i1==i2 faces whose normal is pure rounding error, normalized to unit.
    const float ax = __fsub_rn(vx[1], vx[0]), ay = __fsub_rn(vy[1], vy[0]), az = __fsub_rn(vz[1], vz[0]);
    const float bx = __fsub_rn(vx[2], vx[0]), by = __fsub_rn(vy[2], vy[0]), bz = __fsub_rn(vz[2], vz[0]);
    const float nx = fmaf(ay, bz, -__fmul_rn(az, by));
    const float ny = fmaf(az, bx, -__fmul_rn(ax, bz));
    const float nz = fmaf(ax, by, -__fmul_rn(ay, bx));
    const float nsq = fmaf(nz, nz, fmaf(ny, ny, __fmul_rn(nx, nx)));
    const float nn = __fadd_rn(__fsqrt_rn(nsq), 1e-10f);
    float* no = out + OFF_NORMAL + (b * FF + i) * 3;
    no[0] = __fdiv_rn(nx, nn);
    no[1] = __fdiv_rn(ny, nn);
    no[2] = __fdiv_rn(nz, nn);

    const float x0 = sx[0], y0 = sy[0], x1 = sx[1], y1 = sy[1], x2 = sx[2], y2 = sy[2];
    const float A0 = __fsub_rn(y1, y2), B0 = __fsub_rn(x2, x1);
    const float A1 = __fsub_rn(y2, y0), B1 = __fsub_rn(x0, x2);
    const float denom = __fadd_rn(__fmul_rn(A0, B1), __fmul_rn(B0, __fsub_rn(y0, y2)));
    const bool deg = fabsf(denom) < DEG_EPS;
    const float inv = deg ? 0.0f : __fdiv_rn(1.0f, denom);
    const bool front = (nz > 0.0f) && !deg;

    // stable compaction (order-preserving)
    const unsigned m = __ballot_sync(0xffffffffu, front);
    __shared__ int wcnt[32];
    const int lane = i & 31, wid = i >> 5;
    if (lane == 0) wcnt[wid] = __popc(m);
    __syncthreads();
    int base = 0;
    for (int k = 0; k < wid; k++) base += wcnt[k];
    if (i == 0) {
        int tot = 0;
        for (int k = 0; k < 32; k++) tot += wcnt[k];
        g_cnt[b] = tot;
    }
    if (front) {
        const int pos = base + __popc(m & ((1u << lane) - 1u));
        float* fd = g_face[b][pos];
        float e0[3], e1[3], e2[3];
        edge_eq(x0, y0, x1, y1, x2, y2, e0);
        edge_eq(x1, y1, x2, y2, x0, y0, e1);
        edge_eq(x2, y2, x0, y0, x1, y1, e2);
        // reciprocal of (segment length^2 + 1e-12) per edge, for the
        // division-free distance path (continuous -> rounding-insensitive)
        const float exA = x1 - x0, eyA = y1 - y0;
        const float exB = x2 - x1, eyB = y2 - y1;
        const float exC = x0 - x2, eyC = y0 - y2;
        const float iLA = __fdiv_rn(1.0f, exA * exA + eyA * eyA + 1e-12f);
        const float iLB = __fdiv_rn(1.0f, exB * exB + eyB * eyB + 1e-12f);
        const float iLC = __fdiv_rn(1.0f, exC * exC + eyC * eyC + 1e-12f);
        fd[0]  = fminf(fminf(x0, x1), x2) - SKIP_S;
        fd[1]  = fminf(fminf(y0, y1), y2) - SKIP_S;
        fd[2]  = fmaxf(fmaxf(x0, x1), x2) + SKIP_S;
        fd[3]  = fmaxf(fmaxf(y0, y1), y2) + SKIP_S;
        fd[4]  = e0[0]; fd[5]  = e0[1]; fd[6]  = e0[2]; fd[7]  = e1[0];
        fd[8]  = e1[1]; fd[9]  = e1[2]; fd[10] = e2[0]; fd[11] = e2[1];
        fd[12] = e2[2]; fd[13] = inv;   fd[14] = x2;    fd[15] = y2;
        fd[16] = A0;    fd[17] = B0;    fd[18] = A1;    fd[19] = B1;
        fd[20] = vz[0]; fd[21] = vz[1]; fd[22] = vz[2]; fd[23] = iLA;
        fd[24] = x0;    fd[25] = y0;    fd[26] = x1;    fd[27] = y1;
        fd[28] = iLB;   fd[29] = iLC;   fd[30] = 0.0f;  fd[31] = 0.0f;
        float* cu = g_uv[b][pos];
        cu[0] = uv[(b * PP + i0) * 2 + 0];
        cu[1] = uv[(b * PP + i0) * 2 + 1];
        cu[2] = uv[(b * PP + i1) * 2 + 0];
        cu[3] = uv[(b * PP + i1) * 2 + 1];
        cu[4] = uv[(b * PP + i2) * 2 + 0];
        cu[5] = uv[(b * PP + i2) * 2 + 1];
        cu[6] = 0.0f; cu[7] = 0.0f;
    }
}

// Division-free segment distance^2 (continuous path: free contraction OK)
__device__ __forceinline__ float seg_d2(float px, float py, float ax, float ay,
                                        float bx, float by, float invL2)
{
    const float ex = bx - ax, ey = by - ay;
    const float dax = px - ax, day = py - ay;
    float t = (dax * ex + day * ey) * invL2;
    t = fminf(fmaxf(t, 0.0f), 1.0f);
    const float dx = dax - t * ex;
    const float dy = day - t * ey;
    return dx * dx + dy * dy;
}

// ---------------------------------------------------------------------------
// Raster: 4x4-pixel tiles, 256 threads (16 per pixel).
// Tile-level bbox cull (bit-exact via underflow margin), order-preserving
// compaction into smem with original indices. Boundary path is division-free
// with fast-intrinsic transcendentals. grid = (400, B), block = 256.
// ---------------------------------------------------------------------------
__global__ __launch_bounds__(256) void raster_kernel(const float* __restrict__ texture,
                                                     float* __restrict__ out)
{
    __shared__ __align__(16) float sF[256 * 32];  // 28 staged floats, stride 32
    __shared__ int sIdx[256];
    __shared__ int sWarp[8];

    const int b = blockIdx.y;
    const int tileId = blockIdx.x;                  // 0..399
    const int tx = tileId % 20, ty = tileId / 20;   // 20 x 20 tiles of 4x4
    const int tid = threadIdx.x;
    const int pix = tid >> 4, sub = tid & 15;       // 16 pixels, 16 subs
    const int lw = pix & 3, lh = pix >> 2;
    const int w = tx * 4 + lw;
    const int h = ty * 4 + lh;

    // pixel grid, bit-exact vs jnp separate ops
    const float px = __fsub_rn(__fmul_rn(__fdiv_rn(__fadd_rn((float)w, 0.5f), (float)WW), 2.0f), 1.0f);
    const float py = __fsub_rn(1.0f, __fmul_rn(__fdiv_rn(__fadd_rn((float)h, 0.5f), (float)HH), 2.0f));

    // tile pixel-center extents
    const float tMinX = ((float)(tx * 4) + 0.5f) / (float)WW * 2.0f - 1.0f;
    const float tMaxX = ((float)(tx * 4 + 3) + 0.5f) / (float)WW * 2.0f - 1.0f;
    const float tMaxY = 1.0f - ((float)(ty * 4) + 0.5f) / (float)HH * 2.0f;
    const float tMinY = 1.0f - ((float)(ty * 4 + 3) + 0.5f) / (float)HH * 2.0f;

    const int count = g_cnt[b];
    float bestZ = -1e9f;
    int bestIdx = -1;
    float acc = 0.0f;

    const int lane = tid & 31, wid = tid >> 5;

    for (int cbase = 0; cbase < count; cbase += 256) {
        const int fi = cbase + tid;
        bool keep = false;
        if (fi < count) {
            const float4 bb = *(const float4*)&g_face[b][fi][0];
            keep = !(bb.x > tMaxX || bb.z < tMinX || bb.y > tMaxY || bb.w < tMinY);
        }
        // order-preserving compaction (stable -> argmax first-max semantics hold)
        const unsigned m = __ballot_sync(0xffffffffu, keep);
        if (lane == 0) sWarp[wid] = __popc(m);
        __syncthreads();
        int wbase = 0, tot = 0;
#pragma unroll
        for (int k = 0; k < 8; k++) {
            if (k < wid) wbase += sWarp[k];
            tot += sWarp[k];
        }
        if (keep) {
            const int pos = wbase + __popc(m & ((1u << lane) - 1u));
            const float4* src = (const float4*)&g_face[b][fi][4];
            float4* dst = (float4*)&sF[pos * 32];
#pragma unroll
            for (int k = 0; k < 7; k++) dst[k] = src[k];
            sIdx[pos] = fi;                       // ORIGINAL face row
        }
        __syncthreads();

        for (int j = sub; j < tot; j += 16) {
            const float4* fq = (const float4*)&sF[j * 32];
            const float4 q0 = fq[0];
            const float4 q1 = fq[1];
            const float4 q2 = fq[2];
            // per-pixel skip: max halfplane distance > SKIP_S -> exactly no contribution
            const float s0 = fmaf(q0.x, px, fmaf(q0.y, py, q0.z));
            const float s1 = fmaf(q0.w, px, fmaf(q1.x, py, q1.y));
            const float s2 = fmaf(q1.z, px, fmaf(q1.w, py, q2.x));
            if (fmaxf(s0, fmaxf(s1, s2)) > SKIP_S) continue;

            const float inv = q2.y;
            const float dx2 = __fsub_rn(px, q2.z);
            const float dy2 = __fsub_rn(py, q2.w);
            const float4 q3 = fq[3];
            const float w0 = __fmul_rn(__fadd_rn(__fmul_rn(q3.x, dx2), __fmul_rn(q3.y, dy2)), inv);
            const float w1 = __fmul_rn(__fadd_rn(__fmul_rn(q3.z, dx2), __fmul_rn(q3.w, dy2)), inv);
            const float w2 = __fsub_rn(__fsub_rn(1.0f, w0), w1);
            if (w0 >= 0.0f && w1 >= 0.0f && w2 >= 0.0f) {
                const float4 q4 = fq[4];
                const float z = __fadd_rn(__fadd_rn(__fmul_rn(w0, q4.x),
                                                    __fmul_rn(w1, q4.y)),
                                          __fmul_rn(w2, q4.z));
                if (z > bestZ) { bestZ = z; bestIdx = sIdx[j]; }   // strict > = first-max
            } else {
                // continuous soft-prob path: division-free + fast intrinsics
                const float4 q4 = fq[4];
                const float4 q5 = fq[5];
                const float4 q6 = fq[6];
                float d2 = seg_d2(px, py, q5.x, q5.y, q5.z, q5.w, q4.w);
                d2 = fminf(d2, seg_d2(px, py, q5.z, q5.w, q2.z, q2.w, q6.x));
                d2 = fminf(d2, seg_d2(px, py, q2.z, q2.w, q5.x, q5.y, q6.y));
                const float prob = __expf(d2 * NEG_INV_SIGMA);
                acc += __logf(1.0f - fminf(prob, (float)(1.0 - 1e-7)));
            }
        }
        __syncthreads();
    }

    // width-16 reduction across the 16 threads of a pixel
#pragma unroll
    for (int off = 8; off >= 1; off >>= 1) {
        const float oz = __shfl_down_sync(0xffffffffu, bestZ, off, 16);
        const int   oi = __shfl_down_sync(0xffffffffu, bestIdx, off, 16);
        const float oa = __shfl_down_sync(0xffffffffu, acc, off, 16);
        acc += oa;
        if (oz > bestZ || (oz == bestZ && oi >= 0 && (bestIdx < 0 || oi < bestIdx))) {
            bestZ = oz; bestIdx = oi;
        }
    }

    if (sub == 0) {
        const int pixBase = (b * HH + h) * WW + w;
        float fu = 0.0f, fv = 0.0f, hm = 0.0f, improb;
        if (bestIdx >= 0) {
            improb = 1.0f;
            const float* fd = g_face[b][bestIdx];
            const float inv = fd[13];
            const float dx2 = __fsub_rn(px, fd[14]);
            const float dy2 = __fsub_rn(py, fd[15]);
            const float w0 = __fmul_rn(__fadd_rn(__fmul_rn(fd[16], dx2), __fmul_rn(fd[17], dy2)), inv);
            const float w1 = __fmul_rn(__fadd_rn(__fmul_rn(fd[18], dx2), __fmul_rn(fd[19], dy2)), inv);
            const float w2 = __fsub_rn(__fsub_rn(1.0f, w0), w1);
            const float* cu = g_uv[b][bestIdx];
            fu = __fadd_rn(__fadd_rn(__fmul_rn(w0, cu[0]), __fmul_rn(w1, cu[2])), __fmul_rn(w2, cu[4]));
            fv = __fadd_rn(__fadd_rn(__fmul_rn(w0, cu[1]), __fmul_rn(w1, cu[3])), __fmul_rn(w2, cu[5]));
            hm = __fadd_rn(__fadd_rn(w0, w1), w2);   // mul-by-1 elided like XLA
        } else {
            improb = __fsub_rn(1.0f, expf(acc));     // final exp stays precise
        }

        // fragment: nearest texel, bit-exact chain, rintf = round half-even
        const float gx = __fsub_rn(__fmul_rn(fu, 2.0f), 1.0f);
        const float gy = __fsub_rn(__fmul_rn(fv, 2.0f), 1.0f);
        const float colf = __fmul_rn(__fsub_rn(__fmul_rn(__fadd_rn(gx, 1.0f), (float)TW), 1.0f), 0.5f);
        const float rowf = __fmul_rn(__fsub_rn(__fmul_rn(__fadd_rn(gy, 1.0f), (float)TH), 1.0f), 0.5f);
        const int col = (int)fminf(fmaxf(rintf(colf), 0.0f), (float)(TW - 1));
        const int row = (int)fminf(fmaxf(rintf(rowf), 0.0f), (float)(TH - 1));
        const float* tex = texture + b * 3 * TH * TW;
        out[pixBase * 3 + 0] = __fmul_rn(tex[(0 * TH + row) * TW + col], hm);
        out[pixBase * 3 + 1] = __fmul_rn(tex[(1 * TH + row) * TW + col], hm);
        out[pixBase * 3 + 2] = __fmul_rn(tex[(2 * TH + row) * TW + col], hm);
        out[OFF_IMPROB + pixBase] = improb;
        out[OFF_MASK + pixBase] = hm;
    }
}

extern "C" void kernel_launch(void* const* d_in, const int* in_sizes, int n_in,
                              void* d_out, int out_size)
{
    const float* points  = (const float*)d_in[0];
    const int*   faces   = (const int*)  d_in[1];
    const float* camrot  = (const float*)d_in[2];
    const float* campos  = (const float*)d_in[3];
    const float* camproj = (const float*)d_in[4];
    const float* uv      = (const float*)d_in[5];
    const float* texture = (const float*)d_in[6];
    float* out = (float*)d_out;

    setup_kernel<<<BB, FF>>>(points, faces, camrot, campos, camproj, uv, out);
    raster_kernel<<<dim3(400, BB), 256>>>(texture, out);
}

// round 16
// speedup vs baseline: 1.8550x; 1.8550x over previous
#include <cuda_runtime.h>
#include <cuda_bf16.h>
#include <math.h>

// Fixed shapes
#define BB 2
#define PP 600
#define FF 1024
#define HH 80
#define WW 80
#define TH 256
#define TW 256
#define SIGMA 7e-5f
#define DEG_EPS 1e-8f
#define SKIP_S 0.09f   // distance beyond which expf(-d2/SIGMA) == 0.0f exactly
#define NEG_INV_SIGMA (-1.0f / SIGMA)

// Output layout: imrender (B,H,W,3) | improb (B,H,W,1) | normal1 (B,F,3) | mask (B,H,W,1)
#define OFF_IMPROB (BB*HH*WW*3)
#define OFF_NORMAL (OFF_IMPROB + BB*HH*WW)
#define OFF_MASK   (OFF_NORMAL + BB*FF*3)

// Per-batch compacted front-face rows, 32 floats = 8 float4:
// bb [ 0.. 3] bbox minx,miny,maxx,maxy (expanded by SKIP_S margin)
// q0 [ 4.. 7] e0x,e0y,e0d,e1x
// q1 [ 8..11] e1y,e1d,e2x,e2y
// q2 [12..15] e2d,inv,x2,y2
// q3 [16..19] A0,B0,A1,B1     (A0=y1-y2,B0=x2-x1,A1=y2-y0,B1=x0-x2)
// q4 [20..23] z0,z1,z2,pad
// q5 [24..27] x0,y0,x1,y1
__device__ __align__(16) float g_face[BB][FF][32];
__device__ __align__(16) float g_uv[BB][FF][8];
__device__ int g_cnt[BB];

__device__ __forceinline__ void edge_eq(float ax, float ay, float bx, float by,
                                        float cx, float cy, float* o)
{
    const float ex = bx - ax, ey = by - ay;
    const float L2 = ex * ex + ey * ey;
    if (L2 < 1e-30f) { o[0] = 0.0f; o[1] = 0.0f; o[2] = -1.0f; return; }
    const float rL = rsqrtf(L2);
    float nx = ey * rL, ny = -ex * rL;
    float d = -(nx * ax + ny * ay);
    if (nx * cx + ny * cy + d > 0.0f) { nx = -nx; ny = -ny; d = -d; }
    o[0] = nx; o[1] = ny; o[2] = d;
}

// ---------------------------------------------------------------------------
// Setup: projection, normal1 output (XLA-FMA-contracted cross — load-bearing),
// stable front-face compaction, edge-eq + bbox precompute. grid=(B), block=F
// ---------------------------------------------------------------------------
__global__ void setup_kernel(const float* __restrict__ points,
                             const int*   __restrict__ faces,
                             const float* __restrict__ camrot,
                             const float* __restrict__ campos,
                             const float* __restrict__ camproj,
                             const float* __restrict__ uv,
                             float* __restrict__ out)
{
    const int b = blockIdx.x;
    const int i = threadIdx.x;

    float r[9];
#pragma unroll
    for (int k = 0; k < 9; k++) r[k] = camrot[b * 9 + k];
    const float posx = campos[b * 3 + 0];
    const float posy = campos[b * 3 + 1];
    const float posz = campos[b * 3 + 2];
    const float pr0 = camproj[0], pr1 = camproj[1], pr2 = camproj[2];

    const int i0 = faces[i * 3 + 0];
    const int i1 = faces[i * 3 + 1];
    const int i2 = faces[i * 3 + 2];
    const int idxs[3] = { i0, i1, i2 };

    float vx[3], vy[3], vz[3], sx[3], sy[3];
#pragma unroll
    for (int k = 0; k < 3; k++) {
        const float* p = points + (b * PP + idxs[k]) * 3;
        const float qx = __fsub_rn(p[0], posx);
        const float qy = __fsub_rn(p[1], posy);
        const float qz = __fsub_rn(p[2], posz);
        // camrot is identity in this dataset -> exact regardless of fma
        const float pcx = r[0] * qx + r[1] * qy + r[2] * qz;
        const float pcy = r[3] * qx + r[4] * qy + r[5] * qz;
        const float pcz = r[6] * qx + r[7] * qy + r[8] * qz;
        vx[k] = pcx; vy[k] = pcy; vz[k] = pcz;
        const float zz = __fmul_rn(pcz, pr2);
        sx[k] = __fdiv_rn(__fmul_rn(pcx, pr0), zz);
        sy[k] = __fdiv_rn(__fmul_rn(pcy, pr1), zz);
    }

    // cross(v1-v0, v2-v0) with LLVM-canonical FMA contraction:
    // fsub(fmul x y, fmul c d) -> fma(x, y, -round(c*d)). Load-bearing for
    // i1==i2 faces whose normal is pure rounding error, normalized to unit.
    const float ax = __fsub_rn(vx[1], vx[0]), ay = __fsub_rn(vy[1], vy[0]), az = __fsub_rn(vz[1], vz[0]);
    const float bx = __fsub_rn(vx[2], vx[0]), by = __fsub_rn(vy[2], vy[0]), bz = __fsub_rn(vz[2], vz[0]);
    const float nx = fmaf(ay, bz, -__fmul_rn(az, by));
    const float ny = fmaf(az, bx, -__fmul_rn(ax, bz));
    const float nz = fmaf(ax, by, -__fmul_rn(ay, bx));
    const float nsq = fmaf(nz, nz, fmaf(ny, ny, __fmul_rn(nx, nx)));
    const float nn = __fadd_rn(__fsqrt_rn(nsq), 1e-10f);
    float* no = out + OFF_NORMAL + (b * FF + i) * 3;
    no[0] = __fdiv_rn(nx, nn);
    no[1] = __fdiv_rn(ny, nn);
    no[2] = __fdiv_rn(nz, nn);

    const float x0 = sx[0], y0 = sy[0], x1 = sx[1], y1 = sy[1], x2 = sx[2], y2 = sy[2];
    const float A0 = __fsub_rn(y1, y2), B0 = __fsub_rn(x2, x1);
    const float A1 = __fsub_rn(y2, y0), B1 = __fsub_rn(x0, x2);
    const float denom = __fadd_rn(__fmul_rn(A0, B1), __fmul_rn(B0, __fsub_rn(y0, y2)));
    const bool deg = fabsf(denom) < DEG_EPS;
    const float inv = deg ? 0.0f : __fdiv_rn(1.0f, denom);
    const bool front = (nz > 0.0f) && !deg;

    // stable compaction (order-preserving)
    const unsigned m = __ballot_sync(0xffffffffu, front);
    __shared__ int wcnt[32];
    const int lane = i & 31, wid = i >> 5;
    if (lane == 0) wcnt[wid] = __popc(m);
    __syncthreads();
    int base = 0;
    for (int k = 0; k < wid; k++) base += wcnt[k];
    if (i == 0) {
        int tot = 0;
        for (int k = 0; k < 32; k++) tot += wcnt[k];
        g_cnt[b] = tot;
    }
    if (front) {
        const int pos = base + __popc(m & ((1u << lane) - 1u));
        float* fd = g_face[b][pos];
        float e0[3], e1[3], e2[3];
        edge_eq(x0, y0, x1, y1, x2, y2, e0);
        edge_eq(x1, y1, x2, y2, x0, y0, e1);
        edge_eq(x2, y2, x0, y0, x1, y1, e2);
        fd[0]  = fminf(fminf(x0, x1), x2) - SKIP_S;
        fd[1]  = fminf(fminf(y0, y1), y2) - SKIP_S;
        fd[2]  = fmaxf(fmaxf(x0, x1), x2) + SKIP_S;
        fd[3]  = fmaxf(fmaxf(y0, y1), y2) + SKIP_S;
        fd[4]  = e0[0]; fd[5]  = e0[1]; fd[6]  = e0[2]; fd[7]  = e1[0];
        fd[8]  = e1[1]; fd[9]  = e1[2]; fd[10] = e2[0]; fd[11] = e2[1];
        fd[12] = e2[2]; fd[13] = inv;   fd[14] = x2;    fd[15] = y2;
        fd[16] = A0;    fd[17] = B0;    fd[18] = A1;    fd[19] = B1;
        fd[20] = vz[0]; fd[21] = vz[1]; fd[22] = vz[2]; fd[23] = 0.0f;
        fd[24] = x0;    fd[25] = y0;    fd[26] = x1;    fd[27] = y1;
        fd[28] = 0.0f;  fd[29] = 0.0f;  fd[30] = 0.0f;  fd[31] = 0.0f;
        float* cu = g_uv[b][pos];
        cu[0] = uv[(b * PP + i0) * 2 + 0];
        cu[1] = uv[(b * PP + i0) * 2 + 1];
        cu[2] = uv[(b * PP + i1) * 2 + 0];
        cu[3] = uv[(b * PP + i1) * 2 + 1];
        cu[4] = uv[(b * PP + i2) * 2 + 0];
        cu[5] = uv[(b * PP + i2) * 2 + 1];
        cu[6] = 0.0f; cu[7] = 0.0f;
    }
}

// Segment distance^2, fast-division variant (continuous soft-prob path only;
// ulp-level deviation harmless — validated in R15 at rel_err 7.2e-7)
__device__ __forceinline__ float edge_d2_fast(float px, float py, float axx, float ayy,
                                              float bxx, float byy)
{
    const float ex = bxx - axx, ey = byy - ayy;
    const float L2 = ex * ex + ey * ey + 1e-12f;
    const float dax = px - axx, day = py - ayy;
    float t = __fdividef(dax * ex + day * ey, L2);   // MUFU.RCP + mul
    t = fminf(fmaxf(t, 0.0f), 1.0f);
    const float dx = dax - t * ex;
    const float dy = day - t * ey;
    return dx * dx + dy * dy;
}

// ---------------------------------------------------------------------------
// Raster: 4x4-pixel tiles, 256 threads (16 per pixel).
// Tile-level bbox cull (bit-exact via underflow margin), order-preserving
// compaction into smem with original indices. R12 staging layout: 24 floats,
// STRIDE 28 (gcd(28,32)=4 -> max 2-way bank conflict; stride 32 was the R15
// disaster: all rows on the same banks). grid = (400, B), block = 256.
// ---------------------------------------------------------------------------
__global__ __launch_bounds__(256) void raster_kernel(const float* __restrict__ texture,
                                                     float* __restrict__ out)
{
    __shared__ __align__(16) float sF[256 * 28];  // 24 data floats, stride 28
    __shared__ int sIdx[256];
    __shared__ int sWarp[8];

    const int b = blockIdx.y;
    const int tileId = blockIdx.x;                  // 0..399
    const int tx = tileId % 20, ty = tileId / 20;   // 20 x 20 tiles of 4x4
    const int tid = threadIdx.x;
    const int pix = tid >> 4, sub = tid & 15;       // 16 pixels, 16 subs
    const int lw = pix & 3, lh = pix >> 2;
    const int w = tx * 4 + lw;
    const int h = ty * 4 + lh;

    // pixel grid, bit-exact vs jnp separate ops
    const float px = __fsub_rn(__fmul_rn(__fdiv_rn(__fadd_rn((float)w, 0.5f), (float)WW), 2.0f), 1.0f);
    const float py = __fsub_rn(1.0f, __fmul_rn(__fdiv_rn(__fadd_rn((float)h, 0.5f), (float)HH), 2.0f));

    // tile pixel-center extents
    const float tMinX = ((float)(tx * 4) + 0.5f) / (float)WW * 2.0f - 1.0f;
    const float tMaxX = ((float)(tx * 4 + 3) + 0.5f) / (float)WW * 2.0f - 1.0f;
    const float tMaxY = 1.0f - ((float)(ty * 4) + 0.5f) / (float)HH * 2.0f;
    const float tMinY = 1.0f - ((float)(ty * 4 + 3) + 0.5f) / (float)HH * 2.0f;

    const int count = g_cnt[b];
    float bestZ = -1e9f;
    int bestIdx = -1;
    float acc = 0.0f;

    const int lane = tid & 31, wid = tid >> 5;

    for (int cbase = 0; cbase < count; cbase += 256) {
        const int fi = cbase + tid;
        bool keep = false;
        if (fi < count) {
            const float4 bb = *(const float4*)&g_face[b][fi][0];
            keep = !(bb.x > tMaxX || bb.z < tMinX || bb.y > tMaxY || bb.w < tMinY);
        }
        // order-preserving compaction (stable -> argmax first-max semantics hold)
        const unsigned m = __ballot_sync(0xffffffffu, keep);
        if (lane == 0) sWarp[wid] = __popc(m);
        __syncthreads();
        int wbase = 0, tot = 0;
#pragma unroll
        for (int k = 0; k < 8; k++) {
            if (k < wid) wbase += sWarp[k];
            tot += sWarp[k];
        }
        if (keep) {
            const int pos = wbase + __popc(m & ((1u << lane) - 1u));
            const float4* src = (const float4*)&g_face[b][fi][4];
            float4* dst = (float4*)&sF[pos * 28];
#pragma unroll
            for (int k = 0; k < 6; k++) dst[k] = src[k];
            sIdx[pos] = fi;                       // ORIGINAL face row
        }
        __syncthreads();

        for (int j = sub; j < tot; j += 16) {
            const float4* fq = (const float4*)&sF[j * 28];
            const float4 q0 = fq[0];
            const float4 q1 = fq[1];
            const float4 q2 = fq[2];
            // per-pixel skip: max halfplane distance > SKIP_S -> exactly no contribution
            const float s0 = fmaf(q0.x, px, fmaf(q0.y, py, q0.z));
            const float s1 = fmaf(q0.w, px, fmaf(q1.x, py, q1.y));
            const float s2 = fmaf(q1.z, px, fmaf(q1.w, py, q2.x));
            if (fmaxf(s0, fmaxf(s1, s2)) > SKIP_S) continue;

            const float inv = q2.y;
            const float dx2 = __fsub_rn(px, q2.z);
            const float dy2 = __fsub_rn(py, q2.w);
            const float4 q3 = fq[3];
            const float w0 = __fmul_rn(__fadd_rn(__fmul_rn(q3.x, dx2), __fmul_rn(q3.y, dy2)), inv);
            const float w1 = __fmul_rn(__fadd_rn(__fmul_rn(q3.z, dx2), __fmul_rn(q3.w, dy2)), inv);
            const float w2 = __fsub_rn(__fsub_rn(1.0f, w0), w1);
            if (w0 >= 0.0f && w1 >= 0.0f && w2 >= 0.0f) {
                const float4 q4 = fq[4];
                const float z = __fadd_rn(__fadd_rn(__fmul_rn(w0, q4.x),
                                                    __fmul_rn(w1, q4.y)),
                                          __fmul_rn(w2, q4.z));
                if (z > bestZ) { bestZ = z; bestIdx = sIdx[j]; }   // strict > = first-max
            } else {
                // continuous soft-prob path: fast division + fast intrinsics
                const float4 q5 = fq[5];
                float d2 = edge_d2_fast(px, py, q5.x, q5.y, q5.z, q5.w);
                d2 = fminf(d2, edge_d2_fast(px, py, q5.z, q5.w, q2.z, q2.w));
                d2 = fminf(d2, edge_d2_fast(px, py, q2.z, q2.w, q5.x, q5.y));
                const float prob = __expf(d2 * NEG_INV_SIGMA);
                acc += __logf(1.0f - fminf(prob, (float)(1.0 - 1e-7)));
            }
        }
        __syncthreads();
    }

    // width-16 reduction across the 16 threads of a pixel
#pragma unroll
    for (int off = 8; off >= 1; off >>= 1) {
        const float oz = __shfl_down_sync(0xffffffffu, bestZ, off, 16);
        const int   oi = __shfl_down_sync(0xffffffffu, bestIdx, off, 16);
        const float oa = __shfl_down_sync(0xffffffffu, acc, off, 16);
        acc += oa;
        if (oz > bestZ || (oz == bestZ && oi >= 0 && (bestIdx < 0 || oi < bestIdx))) {
            bestZ = oz; bestIdx = oi;
        }
    }

    if (sub == 0) {
        const int pixBase = (b * HH + h) * WW + w;
        float fu = 0.0f, fv = 0.0f, hm = 0.0f, improb;
        if (bestIdx >= 0) {
            improb = 1.0f;
            const float* fd = g_face[b][bestIdx];
            const float inv = fd[13];
            const float dx2 = __fsub_rn(px, fd[14]);
            const float dy2 = __fsub_rn(py, fd[15]);
            const float w0 = __fmul_rn(__fadd_rn(__fmul_rn(fd[16], dx2), __fmul_rn(fd[17], dy2)), inv);
            const float w1 = __fmul_rn(__fadd_rn(__fmul_rn(fd[18], dx2), __fmul_rn(fd[19], dy2)), inv);
            const float w2 = __fsub_rn(__fsub_rn(1.0f, w0), w1);
            const float* cu = g_uv[b][bestIdx];
            fu = __fadd_rn(__fadd_rn(__fmul_rn(w0, cu[0]), __fmul_rn(w1, cu[2])), __fmul_rn(w2, cu[4]));
            fv = __fadd_rn(__fadd_rn(__fmul_rn(w0, cu[1]), __fmul_rn(w1, cu[3])), __fmul_rn(w2, cu[5]));
            hm = __fadd_rn(__fadd_rn(w0, w1), w2);   // mul-by-1 elided like XLA
        } else {
            improb = __fsub_rn(1.0f, expf(acc));     // final exp stays precise
        }

        // fragment: nearest texel, bit-exact chain, rintf = round half-even
        const float gx = __fsub_rn(__fmul_rn(fu, 2.0f), 1.0f);
        const float gy = __fsub_rn(__fmul_rn(fv, 2.0f), 1.0f);
        const float colf = __fmul_rn(__fsub_rn(__fmul_rn(__fadd_rn(gx, 1.0f), (float)TW), 1.0f), 0.5f);
        const float rowf = __fmul_rn(__fsub_rn(__fmul_rn(__fadd_rn(gy, 1.0f), (float)TH), 1.0f), 0.5f);
        const int col = (int)fminf(fmaxf(rintf(colf), 0.0f), (float)(TW - 1));
        const int row = (int)fminf(fmaxf(rintf(rowf), 0.0f), (float)(TH - 1));
        const float* tex = texture + b * 3 * TH * TW;
        out[pixBase * 3 + 0] = __fmul_rn(tex[(0 * TH + row) * TW + col], hm);
        out[pixBase * 3 + 1] = __fmul_rn(tex[(1 * TH + row) * TW + col], hm);
        out[pixBase * 3 + 2] = __fmul_rn(tex[(2 * TH + row) * TW + col], hm);
        out[OFF_IMPROB + pixBase] = improb;
        out[OFF_MASK + pixBase] = hm;
    }
}

extern "C" void kernel_launch(void* const* d_in, const int* in_sizes, int n_in,
                              void* d_out, int out_size)
{
    const float* points  = (const float*)d_in[0];
    const int*   faces   = (const int*)  d_in[1];
    const float* camrot  = (const float*)d_in[2];
    const float* campos  = (const float*)d_in[3];
    const float* camproj = (const float*)d_in[4];
    const float* uv      = (const float*)d_in[5];
    const float* texture = (const float*)d_in[6];
    float* out = (float*)d_out;

    setup_kernel<<<BB, FF>>>(points, faces, camrot, campos, camproj, uv, out);
    raster_kernel<<<dim3(400, BB), 256>>>(texture, out);
}